// round 11
// baseline (speedup 1.0000x reference)
#include <cuda_runtime.h>

// ---------------------------------------------------------------------------
// B=4096, FEAT=512, EMB=64, HID=1024, NUM_CLASSES=64, LIB=256, OUT_J=256
//   all_state = concat(state, embed[option])            [4096,576]
//   H  = relu(all_state @ [Wx1|Wy1] + b)                [4096,2048]
//   cls = H_x @ Wx2 + bx2 ; H_y @ Wy2 + by2             [4096,512]
//   out_X = cls_X @ NX ; out_Y[b] = cls_Y[b] @ NY[opt]  [4096,256] each
// tf32 mma m16n8k8, operands pre-rounded. 128-thread CTAs, 4 CTAs/SM.
// ---------------------------------------------------------------------------

__device__ float g_H[4096 * 2048];      // tf32-rounded
__device__ float g_cls[4096 * 512];     // tf32-rounded
__device__ float g_state[4096 * 512];   // tf32-rounded copies
__device__ float g_emb[64 * 64];
__device__ float g_W1[576 * 2048];      // [k][ Wx1 | Wy1 ]
__device__ float g_W2[1024 * 512];      // [k][ Wx2 | Wy2 ]
__device__ float g_NX[256 * 256];
__device__ int   g_opt[4096];
__device__ int   g_offsets[65];
__device__ int   g_perm[4096];

static __device__ __forceinline__ float f2tf(float x) {
    unsigned r;
    asm("cvt.rna.tf32.f32 %0, %1;" : "=r"(r) : "f"(x));
    return __uint_as_float(r);
}
static __device__ __forceinline__ unsigned cvt_tf_u(unsigned x) {
    unsigned r;
    asm("cvt.rna.tf32.f32 %0, %1;" : "=r"(r) : "f"(__uint_as_float(x)));
    return r;
}
static __device__ __forceinline__ float4 tf4(float4 v) {
    v.x = f2tf(v.x); v.y = f2tf(v.y); v.z = f2tf(v.z); v.w = f2tf(v.w);
    return v;
}

static __device__ __forceinline__ void mma8(float* c,
    unsigned a0, unsigned a1, unsigned a2, unsigned a3,
    unsigned b0, unsigned b1) {
    asm volatile(
        "mma.sync.aligned.m16n8k8.row.col.f32.tf32.tf32.f32 "
        "{%0,%1,%2,%3},{%4,%5,%6,%7},{%8,%9},{%0,%1,%2,%3};"
        : "+f"(c[0]), "+f"(c[1]), "+f"(c[2]), "+f"(c[3])
        : "r"(a0), "r"(a1), "r"(a2), "r"(a3), "r"(b0), "r"(b1));
}

static __device__ __forceinline__ void cpa16(float* dst, const float* src) {
    unsigned d = (unsigned)__cvta_generic_to_shared(dst);
    asm volatile("cp.async.cg.shared.global [%0], [%1], 16;" :: "r"(d), "l"(src) : "memory");
}
// Zero-fill variant: src_size=0 -> smem gets zeros (src must still be valid).
static __device__ __forceinline__ void cpa16z(float* dst, const float* src, int ok) {
    unsigned d = (unsigned)__cvta_generic_to_shared(dst);
    int sz = ok ? 16 : 0;
    asm volatile("cp.async.cg.shared.global [%0], [%1], 16, %2;"
                 :: "r"(d), "l"(src), "r"(sz) : "memory");
}
#define CPA_COMMIT() asm volatile("cp.async.commit_group;" ::: "memory")
#define CPA_WAIT1()  asm volatile("cp.async.wait_group 1;" ::: "memory")

// ---------------------------------------------------------------------------
// Tile compute, one K=16 stage. A smem [rows][20] (k contig), B smem
// [16][BSTRIDE]. MF m16-frags, NF n8-frags per warp. BCVT: round B frags
// (rna) in-register (bit-identical to rounding at deposit).
// ---------------------------------------------------------------------------
template <int MF, int NF, int BSTRIDE, bool BCVT>
static __device__ __forceinline__ void tile_compute(
    const float* As, const float* Bs, int mOff, int nOff, float acc[][4]) {
    const int lane = threadIdx.x & 31;
    const int g = lane >> 2, t = lane & 3;
    const int rowSel = (lane & 7) + (lane & 8);
    const int colSel = (lane & 16) >> 2;
    const unsigned aBase = (unsigned)__cvta_generic_to_shared(As);
    #pragma unroll
    for (int ks = 0; ks < 16; ks += 8) {
        unsigned a[MF][4];
        #pragma unroll
        for (int mf = 0; mf < MF; mf++) {
            unsigned ad = aBase + 4u * (unsigned)((mOff + mf * 16 + rowSel) * 20 + ks + colSel);
            asm volatile("ldmatrix.sync.aligned.m8n8.x4.shared.b16 {%0,%1,%2,%3}, [%4];"
                : "=r"(a[mf][0]), "=r"(a[mf][1]), "=r"(a[mf][2]), "=r"(a[mf][3])
                : "r"(ad));
        }
        unsigned b[NF][2];
        #pragma unroll
        for (int nf = 0; nf < NF; nf++) {
            const float* bp = Bs + (ks + t) * BSTRIDE + nOff + nf * 8 + g;
            b[nf][0] = __float_as_uint(bp[0]);
            b[nf][1] = __float_as_uint(bp[4 * BSTRIDE]);
            if (BCVT) { b[nf][0] = cvt_tf_u(b[nf][0]); b[nf][1] = cvt_tf_u(b[nf][1]); }
        }
        #pragma unroll
        for (int nf = 0; nf < NF; nf++)
            #pragma unroll
            for (int mf = 0; mf < MF; mf++)
                mma8(acc[mf * NF + nf], a[mf][0], a[mf][1], a[mf][2], a[mf][3],
                     b[nf][0], b[nf][1]);
    }
}

// ---------------------------------------------------------------------------
// k_cvtprep: block 0 = option decode + histogram + offsets + scatter.
// blocks 1..N = tf32 pre-conversion of state/embed/W1/W2/NX (float4 grid-stride).
// ---------------------------------------------------------------------------
#define R0_END 524288    // state       4096*512/4
#define R1_END 525312    // embed       +64*64/4
#define R2_END 820224    // W1          +576*2048/4
#define R3_END 951296    // W2          +1024*512/4
#define R4_END 967680    // NX          +256*256/4

__global__ void k_cvtprep(
    const float* __restrict__ state, const float* __restrict__ embed,
    const float* __restrict__ Wx1, const float* __restrict__ Wy1,
    const float* __restrict__ Wx2, const float* __restrict__ Wy2,
    const float* __restrict__ NX, const int* __restrict__ opt_raw) {
    const int tid = threadIdx.x;
    if (blockIdx.x == 0) {
        __shared__ int s_counts[64];
        __shared__ int s_cursor[64];
        __shared__ int s_flag;
        if (tid == 0) s_flag = 0;
        if (tid < 64) s_counts[tid] = 0;
        __syncthreads();
        int nz = 0;
        for (int w = 1 + 2 * tid; w < 4096; w += 512) nz |= opt_raw[w];
        if (nz) atomicOr(&s_flag, 1);
        __syncthreads();
        const bool is64 = (s_flag == 0);
        for (int i = tid; i < 4096; i += 256) {
            int v = is64 ? opt_raw[2 * i] : opt_raw[i];
            g_opt[i] = v;
            atomicAdd(&s_counts[v], 1);
        }
        __syncthreads();
        if (tid == 0) {
            int acc = 0;
            for (int c = 0; c < 64; c++) {
                g_offsets[c] = acc;
                s_cursor[c]  = acc;
                acc += s_counts[c];
            }
            g_offsets[64] = acc;
        }
        __syncthreads();
        for (int i = tid; i < 4096; i += 256) {
            const int v = g_opt[i];
            const int p = atomicAdd(&s_cursor[v], 1);
            g_perm[p] = i;
        }
        return;
    }
    const int nb = gridDim.x - 1;
    for (long i = (long)(blockIdx.x - 1) * 256 + tid; i < R4_END; i += (long)nb * 256) {
        if (i < R0_END) {
            ((float4*)g_state)[i] = tf4(((const float4*)state)[i]);
        } else if (i < R1_END) {
            long j = i - R0_END;
            ((float4*)g_emb)[j] = tf4(((const float4*)embed)[j]);
        } else if (i < R2_END) {
            long j = i - R1_END;
            int row = (int)(j >> 9), col = ((int)j & 511) * 4;
            const float* src = (col < 1024) ? (Wx1 + row * 1024 + col)
                                            : (Wy1 + row * 1024 + col - 1024);
            *(float4*)(g_W1 + row * 2048 + col) = tf4(*(const float4*)src);
        } else if (i < R3_END) {
            long j = i - R2_END;
            int row = (int)(j >> 7), col = ((int)j & 127) * 4;
            const float* src = (col < 256) ? (Wx2 + row * 256 + col)
                                           : (Wy2 + row * 256 + col - 256);
            *(float4*)(g_W2 + row * 512 + col) = tf4(*(const float4*)src);
        } else {
            long j = i - R3_END;
            ((float4*)g_NX)[j] = tf4(((const float4*)NX)[j]);
        }
    }
}

// Smem stage sizes (floats). A: 128 rows x 20; B: 16 x 72 (n=64 +8 pad).
#define A_ST (128 * 20)
#define B_ST (16 * 72)
#define A_STY (64 * 20)

// ---------------------------------------------------------------------------
// GEMM1: [4096x576] @ g_W1[576x2048] + bias, relu -> g_H (tf32-rounded).
// CTA 128x64, 128 threads (4 warps 2m x 2n, warp tile 64x32). 3-stage cp.async.
// grid (32 n, 32 m) = 1024 blocks.
// ---------------------------------------------------------------------------
__global__ __launch_bounds__(128, 4) void k_gemm1(
    const float* __restrict__ bx1, const float* __restrict__ by1) {
    const int bm = blockIdx.y * 128, bnG = blockIdx.x * 64;
    const float* bias = (bnG < 1024) ? bx1 : by1;
    const int bn = bnG & 1023;

    __shared__ float Asm[3 * A_ST];
    __shared__ float Bsm[3 * B_ST];

    const int tid = threadIdx.x;
    const int warp = tid >> 5;
    const int mOff = (warp >> 1) * 64, nOff = (warp & 1) * 32;
    const int bRow = tid >> 3, bC = (tid & 7) * 8;

    const int grow = bm + tid;
    const float* aState = g_state + (size_t)grow * 512;
    const float* aEmb   = g_emb + g_opt[grow] * 64;

    float acc[16][4];
    #pragma unroll
    for (int i = 0; i < 16; i++)
        #pragma unroll
        for (int j = 0; j < 4; j++) acc[i][j] = 0.f;

    auto issue = [&](int stage, int k0) {
        const float* base = (k0 < 512) ? (aState + k0) : (aEmb + (k0 - 512));
        float* ad = Asm + stage * A_ST + tid * 20;
        cpa16(ad, base); cpa16(ad + 4, base + 4);
        cpa16(ad + 8, base + 8); cpa16(ad + 12, base + 12);
        const float* sb = g_W1 + (size_t)(k0 + bRow) * 2048 + bnG + bC;
        float* bd = Bsm + stage * B_ST + bRow * 72 + bC;
        cpa16(bd, sb); cpa16(bd + 4, sb + 4);
    };

    const int NC = 36;
    issue(0, 0);  CPA_COMMIT();
    issue(1, 16); CPA_COMMIT();
    for (int c = 0; c < NC; c++) {
        CPA_WAIT1();
        __syncthreads();
        if (c + 2 < NC) issue((c + 2) % 3, (c + 2) * 16);
        CPA_COMMIT();
        tile_compute<4, 4, 72, false>(Asm + (c % 3) * A_ST, Bsm + (c % 3) * B_ST,
                                      mOff, nOff, acc);
    }

    const int lane = tid & 31, g = lane >> 2, t = lane & 3;
    #pragma unroll
    for (int mf = 0; mf < 4; mf++)
        #pragma unroll
        for (int nf = 0; nf < 4; nf++) {
            const float* ca = acc[mf * 4 + nf];
            const int ncl = nOff + nf * 8 + 2 * t;
            const float bv0 = bias[bn + ncl], bv1 = bias[bn + ncl + 1];
            const int r0 = bm + mOff + mf * 16 + g;
            float2 o;
            o.x = f2tf(fmaxf(ca[0] + bv0, 0.f)); o.y = f2tf(fmaxf(ca[1] + bv1, 0.f));
            *(float2*)&g_H[(size_t)r0 * 2048 + bnG + ncl] = o;
            o.x = f2tf(fmaxf(ca[2] + bv0, 0.f)); o.y = f2tf(fmaxf(ca[3] + bv1, 0.f));
            *(float2*)&g_H[(size_t)(r0 + 8) * 2048 + bnG + ncl] = o;
        }
}

// ---------------------------------------------------------------------------
// GEMM2: cls = H @ g_W2 + bias (K=1024). CTA 128x64, grid (8, 32) = 256 blocks.
// ---------------------------------------------------------------------------
__global__ __launch_bounds__(128, 4) void k_gemm2(
    const float* __restrict__ bx2, const float* __restrict__ by2) {
    const int bm = blockIdx.y * 128, bnG = blockIdx.x * 64;
    const float* bias = (bnG < 256) ? bx2 : by2;
    const int bn = bnG & 255;
    const int aOff = (bnG < 256) ? 0 : 1024;

    __shared__ float Asm[3 * A_ST];
    __shared__ float Bsm[3 * B_ST];

    const int tid = threadIdx.x;
    const int warp = tid >> 5;
    const int mOff = (warp >> 1) * 64, nOff = (warp & 1) * 32;
    const int bRow = tid >> 3, bC = (tid & 7) * 8;

    const float* aPtr = g_H + (size_t)(bm + tid) * 2048 + aOff;

    float acc[16][4];
    #pragma unroll
    for (int i = 0; i < 16; i++)
        #pragma unroll
        for (int j = 0; j < 4; j++) acc[i][j] = 0.f;

    auto issue = [&](int stage, int k0) {
        float* ad = Asm + stage * A_ST + tid * 20;
        const float* sa = aPtr + k0;
        cpa16(ad, sa); cpa16(ad + 4, sa + 4);
        cpa16(ad + 8, sa + 8); cpa16(ad + 12, sa + 12);
        const float* sb = g_W2 + (size_t)(k0 + bRow) * 512 + bnG + bC;
        float* bd = Bsm + stage * B_ST + bRow * 72 + bC;
        cpa16(bd, sb); cpa16(bd + 4, sb + 4);
    };

    const int NC = 64;
    issue(0, 0);  CPA_COMMIT();
    issue(1, 16); CPA_COMMIT();
    for (int c = 0; c < NC; c++) {
        CPA_WAIT1();
        __syncthreads();
        if (c + 2 < NC) issue((c + 2) % 3, (c + 2) * 16);
        CPA_COMMIT();
        tile_compute<4, 4, 72, false>(Asm + (c % 3) * A_ST, Bsm + (c % 3) * B_ST,
                                      mOff, nOff, acc);
    }

    const int lane = tid & 31, g = lane >> 2, t = lane & 3;
    #pragma unroll
    for (int mf = 0; mf < 4; mf++)
        #pragma unroll
        for (int nf = 0; nf < 4; nf++) {
            const float* ca = acc[mf * 4 + nf];
            const int ncl = nOff + nf * 8 + 2 * t;
            const float bv0 = bias[bn + ncl], bv1 = bias[bn + ncl + 1];
            const int r0 = bm + mOff + mf * 16 + g;
            *(float2*)&g_cls[(size_t)r0 * 512 + bnG + ncl] =
                make_float2(f2tf(ca[0] + bv0), f2tf(ca[1] + bv1));
            *(float2*)&g_cls[(size_t)(r0 + 8) * 512 + bnG + ncl] =
                make_float2(f2tf(ca[2] + bv0), f2tf(ca[3] + bv1));
        }
}

// ---------------------------------------------------------------------------
// GEMM X+Y fused (384 blocks, 128 threads).
//   blocks [0,128):  out_X = cls_X @ g_NX   (CTA 128x64, K=256)
//   blocks [128,384): grouped out_Y (CTA 64x64 per class chunk, K=256;
//                     NY fragments tf32-rounded in-register)
// ---------------------------------------------------------------------------
__global__ __launch_bounds__(128, 4) void k_gemmxy(
    const float* __restrict__ NY, float* __restrict__ out) {
    __shared__ float Asm[3 * A_ST];
    __shared__ float Bsm[3 * B_ST];
    __shared__ int rowIdx[64];

    const int tid = threadIdx.x;
    const int warp = tid >> 5;
    const int lane = tid & 31, g = lane >> 2, t = lane & 3;
    const int bRow = tid >> 3, bC = (tid & 7) * 8;

    if (blockIdx.x < 128) {
        // ----- X path: CTA 128x64 -----
        const int xb = blockIdx.x;
        const int bm = (xb >> 2) * 128, bn = (xb & 3) * 64;
        const int mOff = (warp >> 1) * 64, nOff = (warp & 1) * 32;
        const float* aPtr = g_cls + (size_t)(bm + tid) * 512;

        float acc[16][4];
        #pragma unroll
        for (int i = 0; i < 16; i++)
            #pragma unroll
            for (int j = 0; j < 4; j++) acc[i][j] = 0.f;

        auto issue = [&](int stage, int k0) {
            float* ad = Asm + stage * A_ST + tid * 20;
            const float* sa = aPtr + k0;
            cpa16(ad, sa); cpa16(ad + 4, sa + 4);
            cpa16(ad + 8, sa + 8); cpa16(ad + 12, sa + 12);
            const float* sb = g_NX + (size_t)(k0 + bRow) * 256 + bn + bC;
            float* bd = Bsm + stage * B_ST + bRow * 72 + bC;
            cpa16(bd, sb); cpa16(bd + 4, sb + 4);
        };

        const int NC = 16;
        issue(0, 0);  CPA_COMMIT();
        issue(1, 16); CPA_COMMIT();
        for (int c = 0; c < NC; c++) {
            CPA_WAIT1();
            __syncthreads();
            if (c + 2 < NC) issue((c + 2) % 3, (c + 2) * 16);
            CPA_COMMIT();
            tile_compute<4, 4, 72, false>(Asm + (c % 3) * A_ST, Bsm + (c % 3) * B_ST,
                                          mOff, nOff, acc);
        }
        #pragma unroll
        for (int mf = 0; mf < 4; mf++)
            #pragma unroll
            for (int nf = 0; nf < 4; nf++) {
                const float* ca = acc[mf * 4 + nf];
                const int ncl = nOff + nf * 8 + 2 * t;
                const int r0 = bm + mOff + mf * 16 + g;
                *(float2*)&out[(size_t)r0 * 256 + bn + ncl] = make_float2(ca[0], ca[1]);
                *(float2*)&out[(size_t)(r0 + 8) * 256 + bn + ncl] = make_float2(ca[2], ca[3]);
            }
    } else {
        // ----- Y path: CTA 64x64, warps 2m x 2n, warp tile 32x32 -----
        float* outY = out + (size_t)4096 * 256;
        const int yb = blockIdx.x - 128;
        const int cls = yb >> 2;
        const int bn  = (yb & 3) * 64;
        const int start = g_offsets[cls], end = g_offsets[cls + 1];
        const float* Bmat = NY + (size_t)cls * 65536;

        const int mOff = (warp >> 1) * 32, nOff = (warp & 1) * 32;
        const int aRow = tid >> 1, aC = (tid & 1) * 8;

        for (int chunk = start; chunk < end; chunk += 64) {
            if (tid < 64) rowIdx[tid] = (chunk + tid < end) ? g_perm[chunk + tid] : -1;
            __syncthreads();

            float acc[8][4];
            #pragma unroll
            for (int i = 0; i < 8; i++)
                #pragma unroll
                for (int j = 0; j < 4; j++) acc[i][j] = 0.f;

            const int myRow = rowIdx[aRow];
            const float* aSrc = g_cls + (myRow >= 0 ? (size_t)myRow * 512 + 256 : 0);
            auto issue = [&](int stage, int k0) {
                // Each thread owns 8 A columns (aC..aC+7): TWO 16B cp.asyncs.
                float* ad = Asm + stage * A_STY + aRow * 20 + aC;
                const float* sa = aSrc + k0 + aC;
                cpa16z(ad, sa, myRow >= 0);
                cpa16z(ad + 4, sa + 4, myRow >= 0);
                const float* sb = Bmat + (size_t)(k0 + bRow) * 256 + bn + bC;
                float* bd = Bsm + stage * B_ST + bRow * 72 + bC;
                cpa16(bd, sb); cpa16(bd + 4, sb + 4);
            };

            const int NC = 16;
            issue(0, 0);  CPA_COMMIT();
            issue(1, 16); CPA_COMMIT();
            for (int c = 0; c < NC; c++) {
                CPA_WAIT1();
                __syncthreads();
                if (c + 2 < NC) issue((c + 2) % 3, (c + 2) * 16);
                CPA_COMMIT();
                tile_compute<2, 4, 72, true>(Asm + (c % 3) * A_STY, Bsm + (c % 3) * B_ST,
                                             mOff, nOff, acc);
            }

            #pragma unroll
            for (int mf = 0; mf < 2; mf++)
                #pragma unroll
                for (int nf = 0; nf < 4; nf++) {
                    const float* ca = acc[mf * 4 + nf];
                    const int ncol = bn + nOff + nf * 8 + 2 * t;
                    const int lr = mOff + mf * 16 + g;
                    const int r0 = rowIdx[lr], r1 = rowIdx[lr + 8];
                    if (r0 >= 0)
                        *(float2*)&outY[(size_t)r0 * 256 + ncol] = make_float2(ca[0], ca[1]);
                    if (r1 >= 0)
                        *(float2*)&outY[(size_t)r1 * 256 + ncol] = make_float2(ca[2], ca[3]);
                }
            __syncthreads();  // protect rowIdx / smem before next chunk
        }
    }
}

// ---------------------------------------------------------------------------
// Launch. Inputs: 0 state, 1 option, 2 embed, 3 Wx1, 4 bx1, 5 Wx2, 6 bx2,
// 7 Wy1, 8 by1, 9 Wy2, 10 by2, 11 NX, 12 NY. Output: [out_X | out_Y] fp32.
// ---------------------------------------------------------------------------
extern "C" void kernel_launch(void* const* d_in, const int* in_sizes, int n_in,
                              void* d_out, int out_size) {
    const float* state  = (const float*)d_in[0];
    const int*   optraw = (const int*)d_in[1];
    const float* embed  = (const float*)d_in[2];
    const float* Wx1 = (const float*)d_in[3];
    const float* bx1 = (const float*)d_in[4];
    const float* Wx2 = (const float*)d_in[5];
    const float* bx2 = (const float*)d_in[6];
    const float* Wy1 = (const float*)d_in[7];
    const float* by1 = (const float*)d_in[8];
    const float* Wy2 = (const float*)d_in[9];
    const float* by2 = (const float*)d_in[10];
    const float* NX  = (const float*)d_in[11];
    const float* NY  = (const float*)d_in[12];
    float* out = (float*)d_out;

    k_cvtprep<<<945, 256>>>(state, embed, Wx1, Wy1, Wx2, Wy2, NX, optraw);
    k_gemm1<<<dim3(32, 32), 128>>>(bx1, by1);
    k_gemm2<<<dim3(8, 32), 128>>>(bx2, by2);
    k_gemmxy<<<384, 128>>>(NY, out);
}

// round 12
// speedup vs baseline: 1.0612x; 1.0612x over previous
#include <cuda_runtime.h>

// ---------------------------------------------------------------------------
// B=4096, FEAT=512, EMB=64, HID=1024, NUM_CLASSES=64, LIB=256, OUT_J=256
//   all_state = concat(state, embed[option])            [4096,576]
//   H  = relu(all_state @ [Wx1|Wy1] + b)                [4096,2048]
//   cls = H_x @ Wx2 + bx2 ; H_y @ Wy2 + by2             [4096,512]
//   out_X = cls_X @ NX ; out_Y[b] = cls_Y[b] @ NY[opt]  [4096,256] each
// tf32 mma m16n8k8, operands pre-rounded. 256-thread CTAs (R9 base),
// K-chunk 32 + 2-stage cp.async on gemm1/gemm2/X; Y path = R9 verbatim.
// ---------------------------------------------------------------------------

__device__ float g_H[4096 * 2048];      // tf32-rounded
__device__ float g_cls[4096 * 512];     // tf32-rounded
__device__ float g_state[4096 * 512];   // tf32-rounded copies
__device__ float g_emb[64 * 64];
__device__ float g_W1[576 * 2048];      // [k][ Wx1 | Wy1 ]
__device__ float g_W2[1024 * 512];      // [k][ Wx2 | Wy2 ]
__device__ float g_NX[256 * 256];
__device__ int   g_opt[4096];
__device__ int   g_offsets[65];
__device__ int   g_perm[4096];

static __device__ __forceinline__ float f2tf(float x) {
    unsigned r;
    asm("cvt.rna.tf32.f32 %0, %1;" : "=r"(r) : "f"(x));
    return __uint_as_float(r);
}
static __device__ __forceinline__ unsigned cvt_tf_u(unsigned x) {
    unsigned r;
    asm("cvt.rna.tf32.f32 %0, %1;" : "=r"(r) : "f"(__uint_as_float(x)));
    return r;
}
static __device__ __forceinline__ float4 tf4(float4 v) {
    v.x = f2tf(v.x); v.y = f2tf(v.y); v.z = f2tf(v.z); v.w = f2tf(v.w);
    return v;
}

static __device__ __forceinline__ void mma8(float* c,
    unsigned a0, unsigned a1, unsigned a2, unsigned a3,
    unsigned b0, unsigned b1) {
    asm volatile(
        "mma.sync.aligned.m16n8k8.row.col.f32.tf32.tf32.f32 "
        "{%0,%1,%2,%3},{%4,%5,%6,%7},{%8,%9},{%0,%1,%2,%3};"
        : "+f"(c[0]), "+f"(c[1]), "+f"(c[2]), "+f"(c[3])
        : "r"(a0), "r"(a1), "r"(a2), "r"(a3), "r"(b0), "r"(b1));
}

static __device__ __forceinline__ void cpa16(float* dst, const float* src) {
    unsigned d = (unsigned)__cvta_generic_to_shared(dst);
    asm volatile("cp.async.cg.shared.global [%0], [%1], 16;" :: "r"(d), "l"(src) : "memory");
}
// Zero-fill variant: src_size=0 -> smem gets zeros (src must still be valid).
static __device__ __forceinline__ void cpa16z(float* dst, const float* src, int ok) {
    unsigned d = (unsigned)__cvta_generic_to_shared(dst);
    int sz = ok ? 16 : 0;
    asm volatile("cp.async.cg.shared.global [%0], [%1], 16, %2;"
                 :: "r"(d), "l"(src), "r"(sz) : "memory");
}
#define CPA_COMMIT() asm volatile("cp.async.commit_group;" ::: "memory")
#define CPA_WAIT0()  asm volatile("cp.async.wait_group 0;" ::: "memory")

// ---------------------------------------------------------------------------
// Tile compute, one K=KK stage. A smem [rows][ASTRIDE] (k contig),
// B smem [KK][136]. MF m16-frags, NF n8-frags per warp. BCVT rounds B
// fragments in-register (bit-identical to rounding at deposit).
// ---------------------------------------------------------------------------
template <int MF, int NF, int ASTRIDE, int KK, bool BCVT>
static __device__ __forceinline__ void tile_compute(
    const float* As, const float* Bs, int mOff, int nOff, float acc[][4]) {
    const int lane = threadIdx.x & 31;
    const int g = lane >> 2, t = lane & 3;
    const int rowSel = (lane & 7) + (lane & 8);
    const int colSel = (lane & 16) >> 2;
    const unsigned aBase = (unsigned)__cvta_generic_to_shared(As);
    #pragma unroll
    for (int ks = 0; ks < KK; ks += 8) {
        unsigned a[MF][4];
        #pragma unroll
        for (int mf = 0; mf < MF; mf++) {
            unsigned ad = aBase + 4u * (unsigned)((mOff + mf * 16 + rowSel) * ASTRIDE + ks + colSel);
            asm volatile("ldmatrix.sync.aligned.m8n8.x4.shared.b16 {%0,%1,%2,%3}, [%4];"
                : "=r"(a[mf][0]), "=r"(a[mf][1]), "=r"(a[mf][2]), "=r"(a[mf][3])
                : "r"(ad));
        }
        unsigned b[NF][2];
        #pragma unroll
        for (int nf = 0; nf < NF; nf++) {
            const float* bp = Bs + (ks + t) * 136 + nOff + nf * 8 + g;
            b[nf][0] = __float_as_uint(bp[0]);
            b[nf][1] = __float_as_uint(bp[4 * 136]);
            if (BCVT) { b[nf][0] = cvt_tf_u(b[nf][0]); b[nf][1] = cvt_tf_u(b[nf][1]); }
        }
        #pragma unroll
        for (int nf = 0; nf < NF; nf++)
            #pragma unroll
            for (int mf = 0; mf < MF; mf++)
                mma8(acc[mf * NF + nf], a[mf][0], a[mf][1], a[mf][2], a[mf][3],
                     b[nf][0], b[nf][1]);
    }
}

// ---------------------------------------------------------------------------
// k_cvtprep: block 0 = option decode + histogram + offsets + scatter.
// blocks 1..N = tf32 pre-conversion of state/embed/W1/W2/NX (float4 grid-stride).
// ---------------------------------------------------------------------------
#define R0_END 524288    // state       4096*512/4
#define R1_END 525312    // embed       +64*64/4
#define R2_END 820224    // W1          +576*2048/4
#define R3_END 951296    // W2          +1024*512/4
#define R4_END 967680    // NX          +256*256/4

__global__ void k_cvtprep(
    const float* __restrict__ state, const float* __restrict__ embed,
    const float* __restrict__ Wx1, const float* __restrict__ Wy1,
    const float* __restrict__ Wx2, const float* __restrict__ Wy2,
    const float* __restrict__ NX, const int* __restrict__ opt_raw) {
    const int tid = threadIdx.x;
    if (blockIdx.x == 0) {
        __shared__ int s_counts[64];
        __shared__ int s_cursor[64];
        __shared__ int s_flag;
        if (tid == 0) s_flag = 0;
        if (tid < 64) s_counts[tid] = 0;
        __syncthreads();
        int nz = 0;
        for (int w = 1 + 2 * tid; w < 4096; w += 512) nz |= opt_raw[w];
        if (nz) atomicOr(&s_flag, 1);
        __syncthreads();
        const bool is64 = (s_flag == 0);
        for (int i = tid; i < 4096; i += 256) {
            int v = is64 ? opt_raw[2 * i] : opt_raw[i];
            g_opt[i] = v;
            atomicAdd(&s_counts[v], 1);
        }
        __syncthreads();
        if (tid == 0) {
            int acc = 0;
            for (int c = 0; c < 64; c++) {
                g_offsets[c] = acc;
                s_cursor[c]  = acc;
                acc += s_counts[c];
            }
            g_offsets[64] = acc;
        }
        __syncthreads();
        for (int i = tid; i < 4096; i += 256) {
            const int v = g_opt[i];
            const int p = atomicAdd(&s_cursor[v], 1);
            g_perm[p] = i;
        }
        return;
    }
    const int nb = gridDim.x - 1;
    for (long i = (long)(blockIdx.x - 1) * 256 + tid; i < R4_END; i += (long)nb * 256) {
        if (i < R0_END) {
            ((float4*)g_state)[i] = tf4(((const float4*)state)[i]);
        } else if (i < R1_END) {
            long j = i - R0_END;
            ((float4*)g_emb)[j] = tf4(((const float4*)embed)[j]);
        } else if (i < R2_END) {
            long j = i - R1_END;
            int row = (int)(j >> 9), col = ((int)j & 511) * 4;
            const float* src = (col < 1024) ? (Wx1 + row * 1024 + col)
                                            : (Wy1 + row * 1024 + col - 1024);
            *(float4*)(g_W1 + row * 2048 + col) = tf4(*(const float4*)src);
        } else if (i < R3_END) {
            long j = i - R2_END;
            int row = (int)(j >> 7), col = ((int)j & 127) * 4;
            const float* src = (col < 256) ? (Wx2 + row * 256 + col)
                                           : (Wy2 + row * 256 + col - 256);
            *(float4*)(g_W2 + row * 512 + col) = tf4(*(const float4*)src);
        } else {
            long j = i - R3_END;
            ((float4*)g_NX)[j] = tf4(((const float4*)NX)[j]);
        }
    }
}

// Stage sizes (floats), K-chunk 32. A rows x 36 (32 + 4 pad), B 32 x 136.
#define A1S (128 * 36)
#define A2S (64 * 36)
#define BKS (32 * 136)
#define SMEM_G1 (2 * (A1S + BKS) * 4)   // 71.7 KB
#define SMEM_G2 (2 * (A2S + BKS) * 4)   // 53.2 KB

// ---------------------------------------------------------------------------
// GEMM1: [4096x576] @ g_W1[576x2048] + bias, relu -> g_H (tf32-rounded).
// 128x128 tile, 256 thr, 8 warps (2m x 4n, warp 64x32). K32, 2-stage.
// grid (16, 32) = 512 blocks.
// ---------------------------------------------------------------------------
__global__ __launch_bounds__(256, 2) void k_gemm1(
    const float* __restrict__ bx1, const float* __restrict__ by1) {
    const int bm = blockIdx.y * 128, bnG = blockIdx.x * 128;
    const float* bias = (bnG < 1024) ? bx1 : by1;
    const int bn = bnG & 1023;

    extern __shared__ float smem[];
    float* Asm = smem;
    float* Bsm = smem + 2 * A1S;

    const int tid = threadIdx.x;
    const int warp = tid >> 5;
    const int mOff = (warp >> 2) * 64, nOff = (warp & 3) * 32;
    const int aRow = tid >> 1, aC = (tid & 1) * 16;
    const int bRow = tid >> 3, bC = (tid & 7) * 16;

    const int grow = bm + aRow;
    const float* aState = g_state + (size_t)grow * 512;
    const float* aEmb   = g_emb + g_opt[grow] * 64;

    float acc[16][4];
    #pragma unroll
    for (int i = 0; i < 16; i++)
        #pragma unroll
        for (int j = 0; j < 4; j++) acc[i][j] = 0.f;

    auto issue = [&](int stage, int k0) {
        const int gk = k0 + aC;
        const float* sa = (gk < 512) ? (aState + gk) : (aEmb + (gk - 512));
        float* ad = Asm + stage * A1S + aRow * 36 + aC;
        cpa16(ad, sa); cpa16(ad + 4, sa + 4);
        cpa16(ad + 8, sa + 8); cpa16(ad + 12, sa + 12);
        const float* sb = g_W1 + (size_t)(k0 + bRow) * 2048 + bnG + bC;
        float* bd = Bsm + stage * BKS + bRow * 136 + bC;
        cpa16(bd, sb); cpa16(bd + 4, sb + 4);
        cpa16(bd + 8, sb + 8); cpa16(bd + 12, sb + 12);
    };

    const int NC = 18;  // 576 / 32
    issue(0, 0); CPA_COMMIT();
    for (int c = 0; c < NC; c++) {
        CPA_WAIT0();
        __syncthreads();
        if (c + 1 < NC) { issue((c + 1) & 1, (c + 1) * 32); CPA_COMMIT(); }
        tile_compute<4, 4, 36, 32, false>(Asm + (c & 1) * A1S, Bsm + (c & 1) * BKS,
                                          mOff, nOff, acc);
        __syncthreads();
    }

    const int lane = tid & 31, g = lane >> 2, t = lane & 3;
    #pragma unroll
    for (int mf = 0; mf < 4; mf++)
        #pragma unroll
        for (int nf = 0; nf < 4; nf++) {
            const float* ca = acc[mf * 4 + nf];
            const int ncl = nOff + nf * 8 + 2 * t;
            const float bv0 = bias[bn + ncl], bv1 = bias[bn + ncl + 1];
            const int r0 = bm + mOff + mf * 16 + g;
            float2 o;
            o.x = f2tf(fmaxf(ca[0] + bv0, 0.f)); o.y = f2tf(fmaxf(ca[1] + bv1, 0.f));
            *(float2*)&g_H[(size_t)r0 * 2048 + bnG + ncl] = o;
            o.x = f2tf(fmaxf(ca[2] + bv0, 0.f)); o.y = f2tf(fmaxf(ca[3] + bv1, 0.f));
            *(float2*)&g_H[(size_t)(r0 + 8) * 2048 + bnG + ncl] = o;
        }
}

// ---------------------------------------------------------------------------
// GEMM2: cls = H @ g_W2 + bias (K=1024). 64x128 tile, 256 thr, warps 2m x 4n
// of 32x32. K32, 2-stage. grid (4, 64) = 256 blocks.
// ---------------------------------------------------------------------------
__global__ __launch_bounds__(256, 2) void k_gemm2(
    const float* __restrict__ bx2, const float* __restrict__ by2) {
    const int bm = blockIdx.y * 64, bnG = blockIdx.x * 128;
    const float* bias = (bnG < 256) ? bx2 : by2;
    const int bn = bnG & 255;
    const int aOff = (bnG < 256) ? 0 : 1024;

    extern __shared__ float smem[];
    float* Asm = smem;
    float* Bsm = smem + 2 * A2S;

    const int tid = threadIdx.x;
    const int warp = tid >> 5;
    const int mOff = (warp >> 2) * 32, nOff = (warp & 3) * 32;
    const int aRow = tid >> 2, aC = (tid & 3) * 8;
    const int bRow = tid >> 3, bC = (tid & 7) * 16;

    const float* aPtr = g_H + (size_t)(bm + aRow) * 2048 + aOff;

    float acc[8][4];
    #pragma unroll
    for (int i = 0; i < 8; i++)
        #pragma unroll
        for (int j = 0; j < 4; j++) acc[i][j] = 0.f;

    auto issue = [&](int stage, int k0) {
        const float* sa = aPtr + k0 + aC;
        float* ad = Asm + stage * A2S + aRow * 36 + aC;
        cpa16(ad, sa); cpa16(ad + 4, sa + 4);
        const float* sb = g_W2 + (size_t)(k0 + bRow) * 512 + bnG + bC;
        float* bd = Bsm + stage * BKS + bRow * 136 + bC;
        cpa16(bd, sb); cpa16(bd + 4, sb + 4);
        cpa16(bd + 8, sb + 8); cpa16(bd + 12, sb + 12);
    };

    const int NC = 32;  // 1024 / 32
    issue(0, 0); CPA_COMMIT();
    for (int c = 0; c < NC; c++) {
        CPA_WAIT0();
        __syncthreads();
        if (c + 1 < NC) { issue((c + 1) & 1, (c + 1) * 32); CPA_COMMIT(); }
        tile_compute<2, 4, 36, 32, false>(Asm + (c & 1) * A2S, Bsm + (c & 1) * BKS,
                                          mOff, nOff, acc);
        __syncthreads();
    }

    const int lane = tid & 31, g = lane >> 2, t = lane & 3;
    #pragma unroll
    for (int mf = 0; mf < 2; mf++)
        #pragma unroll
        for (int nf = 0; nf < 4; nf++) {
            const float* ca = acc[mf * 4 + nf];
            const int ncl = nOff + nf * 8 + 2 * t;
            const float bv0 = bias[bn + ncl], bv1 = bias[bn + ncl + 1];
            const int r0 = bm + mOff + mf * 16 + g;
            *(float2*)&g_cls[(size_t)r0 * 512 + bnG + ncl] =
                make_float2(f2tf(ca[0] + bv0), f2tf(ca[1] + bv1));
            *(float2*)&g_cls[(size_t)(r0 + 8) * 512 + bnG + ncl] =
                make_float2(f2tf(ca[2] + bv0), f2tf(ca[3] + bv1));
        }
}

// ---------------------------------------------------------------------------
// GEMM X+Y fused (256 blocks, 256 threads).
//   blocks [0,128):  out_X = cls_X @ g_NX  (64x128 tile, K=256, K32 2-stage)
//   blocks [128,256): grouped out_Y per class (R9-style deposit path, K16)
// ---------------------------------------------------------------------------
__global__ __launch_bounds__(256, 2) void k_gemmxy(
    const float* __restrict__ NY, float* __restrict__ out) {
    extern __shared__ float smem[];
    const int tid = threadIdx.x;
    const int warp = tid >> 5;
    const int lane = tid & 31, g = lane >> 2, t = lane & 3;

    if (blockIdx.x < 128) {
        // ----- X path: 64x128 tile, warps 2m x 4n of 32x32 -----
        const int bm = (blockIdx.x >> 1) * 64, bn = (blockIdx.x & 1) * 128;
        float* Asm = smem;
        float* Bsm = smem + 2 * A2S;
        const int mOff = (warp >> 2) * 32, nOff = (warp & 3) * 32;
        const int aRow = tid >> 2, aC = (tid & 3) * 8;
        const int bRow = tid >> 3, bC = (tid & 7) * 16;
        const float* aPtr = g_cls + (size_t)(bm + aRow) * 512;

        float acc[8][4];
        #pragma unroll
        for (int i = 0; i < 8; i++)
            #pragma unroll
            for (int j = 0; j < 4; j++) acc[i][j] = 0.f;

        auto issue = [&](int stage, int k0) {
            const float* sa = aPtr + k0 + aC;
            float* ad = Asm + stage * A2S + aRow * 36 + aC;
            cpa16(ad, sa); cpa16(ad + 4, sa + 4);
            const float* sb = g_NX + (size_t)(k0 + bRow) * 256 + bn + bC;
            float* bd = Bsm + stage * BKS + bRow * 136 + bC;
            cpa16(bd, sb); cpa16(bd + 4, sb + 4);
            cpa16(bd + 8, sb + 8); cpa16(bd + 12, sb + 12);
        };

        const int NC = 8;  // 256 / 32
        issue(0, 0); CPA_COMMIT();
        for (int c = 0; c < NC; c++) {
            CPA_WAIT0();
            __syncthreads();
            if (c + 1 < NC) { issue((c + 1) & 1, (c + 1) * 32); CPA_COMMIT(); }
            tile_compute<2, 4, 36, 32, false>(Asm + (c & 1) * A2S, Bsm + (c & 1) * BKS,
                                              mOff, nOff, acc);
            __syncthreads();
        }
        #pragma unroll
        for (int mf = 0; mf < 2; mf++)
            #pragma unroll
            for (int nf = 0; nf < 4; nf++) {
                const float* ca = acc[mf * 4 + nf];
                const int ncl = nOff + nf * 8 + 2 * t;
                const int r0 = bm + mOff + mf * 16 + g;
                *(float2*)&out[(size_t)r0 * 256 + bn + ncl] = make_float2(ca[0], ca[1]);
                *(float2*)&out[(size_t)(r0 + 8) * 256 + bn + ncl] = make_float2(ca[2], ca[3]);
            }
    } else {
        // ----- Y path: R9 verbatim. 64-row chunks per class, 64x128 tile -----
        float* outY = out + (size_t)4096 * 256;
        const int yb = blockIdx.x - 128;
        const int cls = yb >> 1;
        const int bn  = (yb & 1) * 128;
        const int start = g_offsets[cls], end = g_offsets[cls + 1];
        const float* Bmat = NY + (size_t)cls * 65536;

        float* AsY = smem;                    // 2 x 64*20
        float* BsY = smem + 2 * (64 * 20);    // 2 x 16*136
        int* rowIdx = (int*)(smem + 2 * (64 * 20) + 2 * (16 * 136));

        const int mOff = (warp >> 2) * 32, nOff = (warp & 3) * 32;
        const int aRow = tid >> 2, aC = (tid & 3) * 4;
        const int bRow = tid >> 4, bC = (tid & 15) * 8;

        for (int chunk = start; chunk < end; chunk += 64) {
            if (tid < 64) rowIdx[tid] = (chunk + tid < end) ? g_perm[chunk + tid] : -1;
            __syncthreads();

            float acc[8][4];
            #pragma unroll
            for (int i = 0; i < 8; i++)
                #pragma unroll
                for (int j = 0; j < 4; j++) acc[i][j] = 0.f;

            float4 pa, pb0, pb1;
            const int myRow = rowIdx[aRow];
            auto fetch = [&](int k0) {
                pa = make_float4(0.f, 0.f, 0.f, 0.f);
                if (myRow >= 0)
                    pa = *(const float4*)(g_cls + (size_t)myRow * 512 + 256 + k0 + aC);
                const float* sb = Bmat + (size_t)(k0 + bRow) * 256 + bn + bC;
                pb0 = *(const float4*)sb; pb1 = *(const float4*)(sb + 4);
            };
            auto deposit = [&](int buf) {
                float* ad = AsY + buf * (64 * 20) + aRow * 20 + aC;
                ad[0] = pa.x; ad[1] = pa.y; ad[2] = pa.z; ad[3] = pa.w;  // g_cls pre-rounded
                float* bd = BsY + buf * (16 * 136) + bRow * 136 + bC;
                bd[0] = f2tf(pb0.x); bd[1] = f2tf(pb0.y); bd[2] = f2tf(pb0.z); bd[3] = f2tf(pb0.w);
                bd[4] = f2tf(pb1.x); bd[5] = f2tf(pb1.y); bd[6] = f2tf(pb1.z); bd[7] = f2tf(pb1.w);
            };

            fetch(0); deposit(0); __syncthreads();
            const int NC = 16;
            for (int c = 0; c < NC; c++) {
                if (c + 1 < NC) fetch((c + 1) * 16);
                tile_compute<2, 4, 20, 16, false>(AsY + (c & 1) * (64 * 20),
                                                  BsY + (c & 1) * (16 * 136),
                                                  mOff, nOff, acc);
                if (c + 1 < NC) deposit((c + 1) & 1);
                __syncthreads();
            }

            #pragma unroll
            for (int mf = 0; mf < 2; mf++)
                #pragma unroll
                for (int nf = 0; nf < 4; nf++) {
                    const float* ca = acc[mf * 4 + nf];
                    const int ncol = bn + nOff + nf * 8 + 2 * t;
                    const int lr = mOff + mf * 16 + g;
                    const int r0 = rowIdx[lr], r1 = rowIdx[lr + 8];
                    if (r0 >= 0)
                        *(float2*)&outY[(size_t)r0 * 256 + ncol] = make_float2(ca[0], ca[1]);
                    if (r1 >= 0)
                        *(float2*)&outY[(size_t)r1 * 256 + ncol] = make_float2(ca[2], ca[3]);
                }
            __syncthreads();  // protect rowIdx / smem before next chunk
        }
    }
}

// ---------------------------------------------------------------------------
// Launch. Inputs: 0 state, 1 option, 2 embed, 3 Wx1, 4 bx1, 5 Wx2, 6 bx2,
// 7 Wy1, 8 by1, 9 Wy2, 10 by2, 11 NX, 12 NY. Output: [out_X | out_Y] fp32.
// ---------------------------------------------------------------------------
extern "C" void kernel_launch(void* const* d_in, const int* in_sizes, int n_in,
                              void* d_out, int out_size) {
    const float* state  = (const float*)d_in[0];
    const int*   optraw = (const int*)d_in[1];
    const float* embed  = (const float*)d_in[2];
    const float* Wx1 = (const float*)d_in[3];
    const float* bx1 = (const float*)d_in[4];
    const float* Wx2 = (const float*)d_in[5];
    const float* bx2 = (const float*)d_in[6];
    const float* Wy1 = (const float*)d_in[7];
    const float* by1 = (const float*)d_in[8];
    const float* Wy2 = (const float*)d_in[9];
    const float* by2 = (const float*)d_in[10];
    const float* NX  = (const float*)d_in[11];
    const float* NY  = (const float*)d_in[12];
    float* out = (float*)d_out;

    // >48KB dynamic smem opt-in (idempotent host calls; no allocation).
    cudaFuncSetAttribute(k_gemm1,  cudaFuncAttributeMaxDynamicSharedMemorySize, SMEM_G1);
    cudaFuncSetAttribute(k_gemm2,  cudaFuncAttributeMaxDynamicSharedMemorySize, SMEM_G2);
    cudaFuncSetAttribute(k_gemmxy, cudaFuncAttributeMaxDynamicSharedMemorySize, SMEM_G2);

    k_cvtprep<<<297, 256>>>(state, embed, Wx1, Wy1, Wx2, Wy2, NX, optraw);
    k_gemm1<<<dim3(16, 32), 256, SMEM_G1>>>(bx1, by1);
    k_gemm2<<<dim3(4, 64), 256, SMEM_G2>>>(bx2, by2);
    k_gemmxy<<<256, 256, SMEM_G2>>>(NY, out);
}

// round 13
// speedup vs baseline: 2.3916x; 2.2538x over previous
#include <cuda_runtime.h>
#include <cuda_fp16.h>

// ---------------------------------------------------------------------------
// B=4096, FEAT=512, EMB=64, HID=1024, NUM_CLASSES=64, LIB=256, OUT_J=256
//   all_state = concat(state, embed[option])            [4096,576]
//   H  = relu(all_state @ [Wx1|Wy1] + b)                [4096,2048]
//   cls = H_x @ Wx2 + bx2 ; H_y @ Wy2 + by2             [4096,512]
//   out_X = cls_X @ NX ; out_Y[b] = cls_Y[b] @ NY[opt]  [4096,256] each
// fp16 mma m16n8k16 (same 10-bit mantissa as tf32), fp32 accum.
// Operands pre-converted to fp16; intermediates stored fp16.
// ---------------------------------------------------------------------------

__device__ __half g_H[4096 * 2048];
__device__ __half g_cls[4096 * 512];
__device__ __half g_state[4096 * 512];
__device__ __half g_emb[64 * 64];
__device__ __half g_W1[576 * 2048];     // [k][ Wx1 | Wy1 ]
__device__ __half g_W2[1024 * 512];     // [k][ Wx2 | Wy2 ]
__device__ __half g_NX[256 * 256];
__device__ int    g_opt[4096];
__device__ int    g_offsets[65];
__device__ int    g_perm[4096];

static __device__ __forceinline__ void st_half4(__half* dst, float4 v) {
    __half2* d = (__half2*)dst;
    d[0] = __floats2half2_rn(v.x, v.y);
    d[1] = __floats2half2_rn(v.z, v.w);
}

static __device__ __forceinline__ void mma16(float* c,
    unsigned a0, unsigned a1, unsigned a2, unsigned a3,
    unsigned b0, unsigned b1) {
    asm volatile(
        "mma.sync.aligned.m16n8k16.row.col.f32.f16.f16.f32 "
        "{%0,%1,%2,%3},{%4,%5,%6,%7},{%8,%9},{%0,%1,%2,%3};"
        : "+f"(c[0]), "+f"(c[1]), "+f"(c[2]), "+f"(c[3])
        : "r"(a0), "r"(a1), "r"(a2), "r"(a3), "r"(b0), "r"(b1));
}

static __device__ __forceinline__ void cpa16(void* dst, const void* src) {
    unsigned d = (unsigned)__cvta_generic_to_shared(dst);
    asm volatile("cp.async.cg.shared.global [%0], [%1], 16;" :: "r"(d), "l"(src) : "memory");
}
#define CPA_COMMIT() asm volatile("cp.async.commit_group;" ::: "memory")
#define CPA_WAIT1()  asm volatile("cp.async.wait_group 1;" ::: "memory")

// ---------------------------------------------------------------------------
// fp16 tile compute, one K=KK stage (KK multiple of 16).
// A smem [rows][ASTRIDE] halves (k contiguous), B smem [KK][136] halves
// (n contiguous). MF m16-frags, NF n8-frags (NF even) per warp.
// A frags: ldmatrix.x4; B frags: ldmatrix.x4.trans (2 n8-blocks per instr).
// ---------------------------------------------------------------------------
template <int MF, int NF, int ASTRIDE, int KK>
static __device__ __forceinline__ void tile_compute_h(
    const __half* As, const __half* Bs, int mOff, int nOff, float acc[][4]) {
    const int lane = threadIdx.x & 31;
    const int aRowSel = lane & 15;             // m row within 16
    const int aColSel = (lane & 16) >> 1;      // 0 or 8 halves (k)
    const int bKSel   = (lane & 7) + ((lane & 8) ? 8 : 0);   // k row within 16
    const int bNSel   = (lane & 16) >> 1;      // 0 or 8 halves (n)
    const unsigned aBase = (unsigned)__cvta_generic_to_shared(As);
    const unsigned bBase = (unsigned)__cvta_generic_to_shared(Bs);
    #pragma unroll
    for (int ks = 0; ks < KK; ks += 16) {
        unsigned a[MF][4];
        #pragma unroll
        for (int mf = 0; mf < MF; mf++) {
            unsigned ad = aBase + 2u * (unsigned)((mOff + mf * 16 + aRowSel) * ASTRIDE + ks + aColSel);
            asm volatile("ldmatrix.sync.aligned.m8n8.x4.shared.b16 {%0,%1,%2,%3}, [%4];"
                : "=r"(a[mf][0]), "=r"(a[mf][1]), "=r"(a[mf][2]), "=r"(a[mf][3])
                : "r"(ad));
        }
        unsigned b[NF][2];
        #pragma unroll
        for (int p = 0; p < NF / 2; p++) {
            unsigned bd = bBase + 2u * (unsigned)((ks + bKSel) * 136 + nOff + p * 16 + bNSel);
            asm volatile("ldmatrix.sync.aligned.m8n8.x4.trans.shared.b16 {%0,%1,%2,%3}, [%4];"
                : "=r"(b[2 * p][0]), "=r"(b[2 * p][1]),
                  "=r"(b[2 * p + 1][0]), "=r"(b[2 * p + 1][1])
                : "r"(bd));
        }
        #pragma unroll
        for (int nf = 0; nf < NF; nf++)
            #pragma unroll
            for (int mf = 0; mf < MF; mf++)
                mma16(acc[mf * NF + nf], a[mf][0], a[mf][1], a[mf][2], a[mf][3],
                      b[nf][0], b[nf][1]);
    }
}

// ---------------------------------------------------------------------------
// k_cvtprep: block 0 = option decode + histogram + offsets + scatter.
// blocks 1..N = fp32 -> fp16 conversion of state/embed/W1/W2/NX.
// ---------------------------------------------------------------------------
#define R0_END 524288    // state       4096*512/4
#define R1_END 525312    // embed       +64*64/4
#define R2_END 820224    // W1          +576*2048/4
#define R3_END 951296    // W2          +1024*512/4
#define R4_END 967680    // NX          +256*256/4

__global__ void k_cvtprep(
    const float* __restrict__ state, const float* __restrict__ embed,
    const float* __restrict__ Wx1, const float* __restrict__ Wy1,
    const float* __restrict__ Wx2, const float* __restrict__ Wy2,
    const float* __restrict__ NX, const int* __restrict__ opt_raw) {
    const int tid = threadIdx.x;
    if (blockIdx.x == 0) {
        __shared__ int s_counts[64];
        __shared__ int s_cursor[64];
        __shared__ int s_flag;
        if (tid == 0) s_flag = 0;
        if (tid < 64) s_counts[tid] = 0;
        __syncthreads();
        int nz = 0;
        for (int w = 1 + 2 * tid; w < 4096; w += 512) nz |= opt_raw[w];
        if (nz) atomicOr(&s_flag, 1);
        __syncthreads();
        const bool is64 = (s_flag == 0);
        for (int i = tid; i < 4096; i += 256) {
            int v = is64 ? opt_raw[2 * i] : opt_raw[i];
            g_opt[i] = v;
            atomicAdd(&s_counts[v], 1);
        }
        __syncthreads();
        if (tid == 0) {
            int acc = 0;
            for (int c = 0; c < 64; c++) {
                g_offsets[c] = acc;
                s_cursor[c]  = acc;
                acc += s_counts[c];
            }
            g_offsets[64] = acc;
        }
        __syncthreads();
        for (int i = tid; i < 4096; i += 256) {
            const int v = g_opt[i];
            const int p = atomicAdd(&s_cursor[v], 1);
            g_perm[p] = i;
        }
        return;
    }
    const int nb = gridDim.x - 1;
    for (long i = (long)(blockIdx.x - 1) * 256 + tid; i < R4_END; i += (long)nb * 256) {
        if (i < R0_END) {
            st_half4(g_state + i * 4, ((const float4*)state)[i]);
        } else if (i < R1_END) {
            long j = i - R0_END;
            st_half4(g_emb + j * 4, ((const float4*)embed)[j]);
        } else if (i < R2_END) {
            long j = i - R1_END;
            int row = (int)(j >> 9), col = ((int)j & 511) * 4;
            const float* src = (col < 1024) ? (Wx1 + row * 1024 + col)
                                            : (Wy1 + row * 1024 + col - 1024);
            st_half4(g_W1 + row * 2048 + col, *(const float4*)src);
        } else if (i < R3_END) {
            long j = i - R2_END;
            int row = (int)(j >> 7), col = ((int)j & 127) * 4;
            const float* src = (col < 256) ? (Wx2 + row * 256 + col)
                                           : (Wy2 + row * 256 + col - 256);
            st_half4(g_W2 + row * 512 + col, *(const float4*)src);
        } else {
            long j = i - R3_END;
            st_half4(g_NX + j * 4, ((const float4*)NX)[j]);
        }
    }
}

// Stage sizes in halves. K-chunk 32. A rows x 40 (32 + 8 pad), B 32 x 136.
#define A1S (128 * 40)
#define A2S (64 * 40)
#define BKS (32 * 136)
#define SMEM_G1_BYTES (3 * (A1S + BKS) * 2)   // 56.8 KB -> dynamic

// ---------------------------------------------------------------------------
// GEMM1: [4096x576] @ g_W1[576x2048] + bias, relu -> g_H (fp16).
// 128x128 tile, 256 thr, warps 2m x 4n (64x32). K32, 3-stage cp.async.
// grid (16, 32) = 512 blocks.
// ---------------------------------------------------------------------------
__global__ __launch_bounds__(256, 2) void k_gemm1(
    const float* __restrict__ bx1, const float* __restrict__ by1) {
    const int bm = blockIdx.y * 128, bnG = blockIdx.x * 128;
    const float* bias = (bnG < 1024) ? bx1 : by1;
    const int bn = bnG & 1023;

    extern __shared__ __half smem[];
    __half* Asm = smem;
    __half* Bsm = smem + 3 * A1S;

    const int tid = threadIdx.x;
    const int warp = tid >> 5;
    const int mOff = (warp >> 2) * 64, nOff = (warp & 3) * 32;
    const int aRow = tid >> 1, aC = (tid & 1) * 16;   // halves
    const int bRow = tid >> 3, bC = (tid & 7) * 16;   // halves

    const int grow = bm + aRow;
    const __half* aState = g_state + (size_t)grow * 512;
    const __half* aEmb   = g_emb + g_opt[grow] * 64;

    float acc[16][4];
    #pragma unroll
    for (int i = 0; i < 16; i++)
        #pragma unroll
        for (int j = 0; j < 4; j++) acc[i][j] = 0.f;

    auto issue = [&](int stage, int k0) {
        const int gk = k0 + aC;
        const __half* sa = (gk < 512) ? (aState + gk) : (aEmb + (gk - 512));
        __half* ad = Asm + stage * A1S + aRow * 40 + aC;
        cpa16(ad, sa); cpa16(ad + 8, sa + 8);
        const __half* sb = g_W1 + (size_t)(k0 + bRow) * 2048 + bnG + bC;
        __half* bd = Bsm + stage * BKS + bRow * 136 + bC;
        cpa16(bd, sb); cpa16(bd + 8, sb + 8);
    };

    const int NC = 18;  // 576 / 32
    issue(0, 0);  CPA_COMMIT();
    issue(1, 32); CPA_COMMIT();
    for (int c = 0; c < NC; c++) {
        CPA_WAIT1();
        __syncthreads();
        if (c + 2 < NC) issue((c + 2) % 3, (c + 2) * 32);
        CPA_COMMIT();
        tile_compute_h<4, 4, 40, 32>(Asm + (c % 3) * A1S, Bsm + (c % 3) * BKS,
                                     mOff, nOff, acc);
    }

    const int lane = tid & 31, g = lane >> 2, t = lane & 3;
    #pragma unroll
    for (int mf = 0; mf < 4; mf++)
        #pragma unroll
        for (int nf = 0; nf < 4; nf++) {
            const float* ca = acc[mf * 4 + nf];
            const int ncl = nOff + nf * 8 + 2 * t;
            const float bv0 = bias[bn + ncl], bv1 = bias[bn + ncl + 1];
            const int r0 = bm + mOff + mf * 16 + g;
            *(__half2*)&g_H[(size_t)r0 * 2048 + bnG + ncl] =
                __floats2half2_rn(fmaxf(ca[0] + bv0, 0.f), fmaxf(ca[1] + bv1, 0.f));
            *(__half2*)&g_H[(size_t)(r0 + 8) * 2048 + bnG + ncl] =
                __floats2half2_rn(fmaxf(ca[2] + bv0, 0.f), fmaxf(ca[3] + bv1, 0.f));
        }
}

// ---------------------------------------------------------------------------
// GEMM2: cls = H @ g_W2 + bias (K=1024). 64x128 tile, 256 thr,
// warps 2m x 4n of 32x32. K32, 3-stage. grid (4, 64) = 256 blocks.
// ---------------------------------------------------------------------------
__global__ __launch_bounds__(256, 2) void k_gemm2(
    const float* __restrict__ bx2, const float* __restrict__ by2) {
    const int bm = blockIdx.y * 64, bnG = blockIdx.x * 128;
    const float* bias = (bnG < 256) ? bx2 : by2;
    const int bn = bnG & 255;
    const int aOff = (bnG < 256) ? 0 : 1024;

    __shared__ __half Asm[3 * A2S];
    __shared__ __half Bsm[3 * BKS];

    const int tid = threadIdx.x;
    const int warp = tid >> 5;
    const int mOff = (warp >> 2) * 32, nOff = (warp & 3) * 32;
    const int aRow = tid >> 2, aC = (tid & 3) * 8;
    const int bRow = tid >> 3, bC = (tid & 7) * 16;

    const __half* aPtr = g_H + (size_t)(bm + aRow) * 2048 + aOff;

    float acc[8][4];
    #pragma unroll
    for (int i = 0; i < 8; i++)
        #pragma unroll
        for (int j = 0; j < 4; j++) acc[i][j] = 0.f;

    auto issue = [&](int stage, int k0) {
        __half* ad = Asm + stage * A2S + aRow * 40 + aC;
        cpa16(ad, aPtr + k0 + aC);
        const __half* sb = g_W2 + (size_t)(k0 + bRow) * 512 + bnG + bC;
        __half* bd = Bsm + stage * BKS + bRow * 136 + bC;
        cpa16(bd, sb); cpa16(bd + 8, sb + 8);
    };

    const int NC = 32;  // 1024 / 32
    issue(0, 0);  CPA_COMMIT();
    issue(1, 32); CPA_COMMIT();
    for (int c = 0; c < NC; c++) {
        CPA_WAIT1();
        __syncthreads();
        if (c + 2 < NC) issue((c + 2) % 3, (c + 2) * 32);
        CPA_COMMIT();
        tile_compute_h<2, 4, 40, 32>(Asm + (c % 3) * A2S, Bsm + (c % 3) * BKS,
                                     mOff, nOff, acc);
    }

    const int lane = tid & 31, g = lane >> 2, t = lane & 3;
    #pragma unroll
    for (int mf = 0; mf < 2; mf++)
        #pragma unroll
        for (int nf = 0; nf < 4; nf++) {
            const float* ca = acc[mf * 4 + nf];
            const int ncl = nOff + nf * 8 + 2 * t;
            const float bv0 = bias[bn + ncl], bv1 = bias[bn + ncl + 1];
            const int r0 = bm + mOff + mf * 16 + g;
            *(__half2*)&g_cls[(size_t)r0 * 512 + bnG + ncl] =
                __floats2half2_rn(ca[0] + bv0, ca[1] + bv1);
            *(__half2*)&g_cls[(size_t)(r0 + 8) * 512 + bnG + ncl] =
                __floats2half2_rn(ca[2] + bv0, ca[3] + bv1);
        }
}

// Y-path stage sizes (halves): A 64 x 24 (k16 + 8 pad), B 16 x 136.
#define AYS (64 * 24)
#define BYS (16 * 136)

// ---------------------------------------------------------------------------
// GEMM X+Y fused (256 blocks, 256 threads).
//   blocks [0,128):  out_X = cls_X @ g_NX  (64x128 tile, K=256, K32 3-stage)
//   blocks [128,256): grouped out_Y per class (reg-deposit path, K16 chunks;
//                     NY fp32 -> fp16 at deposit)
// ---------------------------------------------------------------------------
__global__ __launch_bounds__(256, 2) void k_gemmxy(
    const float* __restrict__ NY, float* __restrict__ out) {
    __shared__ __half smem[3 * (A2S + BKS)];
    __shared__ int rowIdx[64];

    const int tid = threadIdx.x;
    const int warp = tid >> 5;
    const int lane = tid & 31, g = lane >> 2, t = lane & 3;

    if (blockIdx.x < 128) {
        // ----- X path: 64x128 tile, warps 2m x 4n of 32x32 -----
        const int bm = (blockIdx.x >> 1) * 64, bn = (blockIdx.x & 1) * 128;
        __half* Asm = smem;
        __half* Bsm = smem + 3 * A2S;
        const int mOff = (warp >> 2) * 32, nOff = (warp & 3) * 32;
        const int aRow = tid >> 2, aC = (tid & 3) * 8;
        const int bRow = tid >> 3, bC = (tid & 7) * 16;
        const __half* aPtr = g_cls + (size_t)(bm + aRow) * 512;

        float acc[8][4];
        #pragma unroll
        for (int i = 0; i < 8; i++)
            #pragma unroll
            for (int j = 0; j < 4; j++) acc[i][j] = 0.f;

        auto issue = [&](int stage, int k0) {
            __half* ad = Asm + stage * A2S + aRow * 40 + aC;
            cpa16(ad, aPtr + k0 + aC);
            const __half* sb = g_NX + (size_t)(k0 + bRow) * 256 + bn + bC;
            __half* bd = Bsm + stage * BKS + bRow * 136 + bC;
            cpa16(bd, sb); cpa16(bd + 8, sb + 8);
        };

        const int NC = 8;  // 256 / 32
        issue(0, 0);  CPA_COMMIT();
        issue(1, 32); CPA_COMMIT();
        for (int c = 0; c < NC; c++) {
            CPA_WAIT1();
            __syncthreads();
            if (c + 2 < NC) issue((c + 2) % 3, (c + 2) * 32);
            CPA_COMMIT();
            tile_compute_h<2, 4, 40, 32>(Asm + (c % 3) * A2S, Bsm + (c % 3) * BKS,
                                         mOff, nOff, acc);
        }
        #pragma unroll
        for (int mf = 0; mf < 2; mf++)
            #pragma unroll
            for (int nf = 0; nf < 4; nf++) {
                const float* ca = acc[mf * 4 + nf];
                const int ncl = nOff + nf * 8 + 2 * t;
                const int r0 = bm + mOff + mf * 16 + g;
                *(float2*)&out[(size_t)r0 * 256 + bn + ncl] = make_float2(ca[0], ca[1]);
                *(float2*)&out[(size_t)(r0 + 8) * 256 + bn + ncl] = make_float2(ca[2], ca[3]);
            }
    } else {
        // ----- Y path: 64-row chunks per class, 64x128 tile, K16 chunks -----
        float* outY = out + (size_t)4096 * 256;
        const int yb = blockIdx.x - 128;
        const int cls = yb >> 1;
        const int bn  = (yb & 1) * 128;
        const int start = g_offsets[cls], end = g_offsets[cls + 1];
        const float* Bmat = NY + (size_t)cls * 65536;

        __half* AsY = smem;                 // 2 x AYS
        __half* BsY = smem + 2 * AYS;       // 2 x BYS

        const int mOff = (warp >> 2) * 32, nOff = (warp & 3) * 32;
        const int aRow = tid >> 2, aC = (tid & 3) * 4;   // 4 halves per thread
        const int bRow = tid >> 4, bC = (tid & 15) * 8;  // 8 floats -> 8 halves

        for (int chunk = start; chunk < end; chunk += 64) {
            if (tid < 64) rowIdx[tid] = (chunk + tid < end) ? g_perm[chunk + tid] : -1;
            __syncthreads();

            float acc[8][4];
            #pragma unroll
            for (int i = 0; i < 8; i++)
                #pragma unroll
                for (int j = 0; j < 4; j++) acc[i][j] = 0.f;

            __half2 pa01, pa23;
            float4 pb0, pb1;
            const int myRow = rowIdx[aRow];
            const __half* aSrc = g_cls + (myRow >= 0 ? (size_t)myRow * 512 + 256 : 0);
            auto fetch = [&](int k0) {
                if (myRow >= 0) {
                    const __half* s = aSrc + k0 + aC;
                    pa01 = *(const __half2*)s;
                    pa23 = *(const __half2*)(s + 2);
                } else {
                    pa01 = __floats2half2_rn(0.f, 0.f);
                    pa23 = pa01;
                }
                const float* sb = Bmat + (size_t)(k0 + bRow) * 256 + bn + bC;
                pb0 = *(const float4*)sb; pb1 = *(const float4*)(sb + 4);
            };
            auto deposit = [&](int buf) {
                __half* ad = AsY + buf * AYS + aRow * 24 + aC;
                *(__half2*)ad = pa01;
                *(__half2*)(ad + 2) = pa23;
                __half* bd = BsY + buf * BYS + bRow * 136 + bC;
                st_half4(bd, pb0);
                st_half4(bd + 4, pb1);
            };

            fetch(0); deposit(0); __syncthreads();
            const int NC = 16;  // 256 / 16
            for (int c = 0; c < NC; c++) {
                if (c + 1 < NC) fetch((c + 1) * 16);
                tile_compute_h<2, 4, 24, 16>(AsY + (c & 1) * AYS, BsY + (c & 1) * BYS,
                                             mOff, nOff, acc);
                if (c + 1 < NC) deposit((c + 1) & 1);
                __syncthreads();
            }

            #pragma unroll
            for (int mf = 0; mf < 2; mf++)
                #pragma unroll
                for (int nf = 0; nf < 4; nf++) {
                    const float* ca = acc[mf * 4 + nf];
                    const int ncol = bn + nOff + nf * 8 + 2 * t;
                    const int lr = mOff + mf * 16 + g;
                    const int r0 = rowIdx[lr], r1 = rowIdx[lr + 8];
                    if (r0 >= 0)
                        *(float2*)&outY[(size_t)r0 * 256 + ncol] = make_float2(ca[0], ca[1]);
                    if (r1 >= 0)
                        *(float2*)&outY[(size_t)r1 * 256 + ncol] = make_float2(ca[2], ca[3]);
                }
            __syncthreads();  // protect rowIdx / smem before next chunk
        }
    }
}

// ---------------------------------------------------------------------------
// Launch. Inputs: 0 state, 1 option, 2 embed, 3 Wx1, 4 bx1, 5 Wx2, 6 bx2,
// 7 Wy1, 8 by1, 9 Wy2, 10 by2, 11 NX, 12 NY. Output: [out_X | out_Y] fp32.
// ---------------------------------------------------------------------------
extern "C" void kernel_launch(void* const* d_in, const int* in_sizes, int n_in,
                              void* d_out, int out_size) {
    const float* state  = (const float*)d_in[0];
    const int*   optraw = (const int*)d_in[1];
    const float* embed  = (const float*)d_in[2];
    const float* Wx1 = (const float*)d_in[3];
    const float* bx1 = (const float*)d_in[4];
    const float* Wx2 = (const float*)d_in[5];
    const float* bx2 = (const float*)d_in[6];
    const float* Wy1 = (const float*)d_in[7];
    const float* by1 = (const float*)d_in[8];
    const float* Wy2 = (const float*)d_in[9];
    const float* by2 = (const float*)d_in[10];
    const float* NX  = (const float*)d_in[11];
    const float* NY  = (const float*)d_in[12];
    float* out = (float*)d_out;

    // >48KB dynamic smem opt-in for gemm1 (idempotent host call; no alloc).
    cudaFuncSetAttribute(k_gemm1, cudaFuncAttributeMaxDynamicSharedMemorySize,
                         SMEM_G1_BYTES);

    k_cvtprep<<<297, 256>>>(state, embed, Wx1, Wy1, Wx2, Wy2, NX, optraw);
    k_gemm1<<<dim3(16, 32), 256, SMEM_G1_BYTES>>>(bx1, by1);
    k_gemm2<<<dim3(4, 64), 256>>>(bx2, by2);
    k_gemmxy<<<256, 256>>>(NY, out);
}

// round 14
// speedup vs baseline: 2.5131x; 1.0508x over previous
#include <cuda_runtime.h>
#include <cuda_fp16.h>

// ---------------------------------------------------------------------------
// B=4096, FEAT=512, EMB=64, HID=1024, NUM_CLASSES=64, LIB=256, OUT_J=256
//   all_state = concat(state, embed[option])            [4096,576]
//   H  = relu(all_state @ [Wx1|Wy1] + b)                [4096,2048]
//   cls = H_x @ Wx2 + bx2 ; H_y @ Wy2 + by2             [4096,512]
//   out_X = cls_X @ NX ; out_Y[b] = cls_Y[b] @ NY[opt]  [4096,256] each
// fp16 mma m16n8k16, fp32 accum. All operands pre-converted to fp16
// (incl. NY); every GEMM mainloop is a 3-stage cp.async pipeline.
// ---------------------------------------------------------------------------

__device__ __half g_H[4096 * 2048];
__device__ __half g_cls[4096 * 512];
__device__ __half g_state[4096 * 512];
__device__ __half g_emb[64 * 64];
__device__ __half g_W1[576 * 2048];     // [k][ Wx1 | Wy1 ]
__device__ __half g_W2[1024 * 512];     // [k][ Wx2 | Wy2 ]
__device__ __half g_NX[256 * 256];
__device__ __half g_NY[64 * 256 * 256];
__device__ int    g_opt[4096];
__device__ int    g_offsets[65];
__device__ int    g_perm[4096];

static __device__ __forceinline__ void st_half4(__half* dst, float4 v) {
    __half2* d = (__half2*)dst;
    d[0] = __floats2half2_rn(v.x, v.y);
    d[1] = __floats2half2_rn(v.z, v.w);
}

static __device__ __forceinline__ void mma16(float* c,
    unsigned a0, unsigned a1, unsigned a2, unsigned a3,
    unsigned b0, unsigned b1) {
    asm volatile(
        "mma.sync.aligned.m16n8k16.row.col.f32.f16.f16.f32 "
        "{%0,%1,%2,%3},{%4,%5,%6,%7},{%8,%9},{%0,%1,%2,%3};"
        : "+f"(c[0]), "+f"(c[1]), "+f"(c[2]), "+f"(c[3])
        : "r"(a0), "r"(a1), "r"(a2), "r"(a3), "r"(b0), "r"(b1));
}

static __device__ __forceinline__ void cpa16(void* dst, const void* src) {
    unsigned d = (unsigned)__cvta_generic_to_shared(dst);
    asm volatile("cp.async.cg.shared.global [%0], [%1], 16;" :: "r"(d), "l"(src) : "memory");
}
// Zero-fill variant: src-size 0 -> smem gets zeros (src must stay valid).
static __device__ __forceinline__ void cpa16z(void* dst, const void* src, int ok) {
    unsigned d = (unsigned)__cvta_generic_to_shared(dst);
    int sz = ok ? 16 : 0;
    asm volatile("cp.async.cg.shared.global [%0], [%1], 16, %2;"
                 :: "r"(d), "l"(src), "r"(sz) : "memory");
}
#define CPA_COMMIT() asm volatile("cp.async.commit_group;" ::: "memory")
#define CPA_WAIT1()  asm volatile("cp.async.wait_group 1;" ::: "memory")

// ---------------------------------------------------------------------------
// fp16 tile compute, one K=KK stage (KK multiple of 16).
// A smem [rows][ASTRIDE] halves (k contiguous), B smem [KK][136] halves
// (n contiguous). MF m16-frags, NF n8-frags (NF even) per warp.
// ---------------------------------------------------------------------------
template <int MF, int NF, int ASTRIDE, int KK>
static __device__ __forceinline__ void tile_compute_h(
    const __half* As, const __half* Bs, int mOff, int nOff, float acc[][4]) {
    const int lane = threadIdx.x & 31;
    const int aRowSel = lane & 15;
    const int aColSel = (lane & 16) >> 1;
    const int bKSel   = lane & 15;
    const int bNSel   = (lane & 16) >> 1;
    const unsigned aBase = (unsigned)__cvta_generic_to_shared(As);
    const unsigned bBase = (unsigned)__cvta_generic_to_shared(Bs);
    #pragma unroll
    for (int ks = 0; ks < KK; ks += 16) {
        unsigned a[MF][4];
        #pragma unroll
        for (int mf = 0; mf < MF; mf++) {
            unsigned ad = aBase + 2u * (unsigned)((mOff + mf * 16 + aRowSel) * ASTRIDE + ks + aColSel);
            asm volatile("ldmatrix.sync.aligned.m8n8.x4.shared.b16 {%0,%1,%2,%3}, [%4];"
                : "=r"(a[mf][0]), "=r"(a[mf][1]), "=r"(a[mf][2]), "=r"(a[mf][3])
                : "r"(ad));
        }
        unsigned b[NF][2];
        #pragma unroll
        for (int p = 0; p < NF / 2; p++) {
            unsigned bd = bBase + 2u * (unsigned)((ks + bKSel) * 136 + nOff + p * 16 + bNSel);
            asm volatile("ldmatrix.sync.aligned.m8n8.x4.trans.shared.b16 {%0,%1,%2,%3}, [%4];"
                : "=r"(b[2 * p][0]), "=r"(b[2 * p][1]),
                  "=r"(b[2 * p + 1][0]), "=r"(b[2 * p + 1][1])
                : "r"(bd));
        }
        #pragma unroll
        for (int nf = 0; nf < NF; nf++)
            #pragma unroll
            for (int mf = 0; mf < MF; mf++)
                mma16(acc[mf * NF + nf], a[mf][0], a[mf][1], a[mf][2], a[mf][3],
                      b[nf][0], b[nf][1]);
    }
}

// ---------------------------------------------------------------------------
// k_cvtprep: block 0 = option decode + histogram + offsets + scatter.
// blocks 1..N = fp32 -> fp16 conversion of state/embed/W1/W2/NX/NY.
// ---------------------------------------------------------------------------
#define R0_END 524288     // state       4096*512/4
#define R1_END 525312     // embed       +64*64/4
#define R2_END 820224     // W1          +576*2048/4
#define R3_END 951296     // W2          +1024*512/4
#define R4_END 967680     // NX          +256*256/4
#define R5_END 2016256    // NY          +64*256*256/4

__global__ void k_cvtprep(
    const float* __restrict__ state, const float* __restrict__ embed,
    const float* __restrict__ Wx1, const float* __restrict__ Wy1,
    const float* __restrict__ Wx2, const float* __restrict__ Wy2,
    const float* __restrict__ NX, const float* __restrict__ NY,
    const int* __restrict__ opt_raw) {
    const int tid = threadIdx.x;
    if (blockIdx.x == 0) {
        __shared__ int s_counts[64];
        __shared__ int s_cursor[64];
        __shared__ int s_flag;
        if (tid == 0) s_flag = 0;
        if (tid < 64) s_counts[tid] = 0;
        __syncthreads();
        int nz = 0;
        for (int w = 1 + 2 * tid; w < 4096; w += 512) nz |= opt_raw[w];
        if (nz) atomicOr(&s_flag, 1);
        __syncthreads();
        const bool is64 = (s_flag == 0);
        for (int i = tid; i < 4096; i += 256) {
            int v = is64 ? opt_raw[2 * i] : opt_raw[i];
            g_opt[i] = v;
            atomicAdd(&s_counts[v], 1);
        }
        __syncthreads();
        if (tid == 0) {
            int acc = 0;
            for (int c = 0; c < 64; c++) {
                g_offsets[c] = acc;
                s_cursor[c]  = acc;
                acc += s_counts[c];
            }
            g_offsets[64] = acc;
        }
        __syncthreads();
        for (int i = tid; i < 4096; i += 256) {
            const int v = g_opt[i];
            const int p = atomicAdd(&s_cursor[v], 1);
            g_perm[p] = i;
        }
        return;
    }
    const int nb = gridDim.x - 1;
    for (long i = (long)(blockIdx.x - 1) * 256 + tid; i < R5_END; i += (long)nb * 256) {
        if (i < R0_END) {
            st_half4(g_state + i * 4, ((const float4*)state)[i]);
        } else if (i < R1_END) {
            long j = i - R0_END;
            st_half4(g_emb + j * 4, ((const float4*)embed)[j]);
        } else if (i < R2_END) {
            long j = i - R1_END;
            int row = (int)(j >> 9), col = ((int)j & 511) * 4;
            const float* src = (col < 1024) ? (Wx1 + row * 1024 + col)
                                            : (Wy1 + row * 1024 + col - 1024);
            st_half4(g_W1 + row * 2048 + col, *(const float4*)src);
        } else if (i < R3_END) {
            long j = i - R2_END;
            int row = (int)(j >> 7), col = ((int)j & 127) * 4;
            const float* src = (col < 256) ? (Wx2 + row * 256 + col)
                                           : (Wy2 + row * 256 + col - 256);
            st_half4(g_W2 + row * 512 + col, *(const float4*)src);
        } else if (i < R4_END) {
            long j = i - R3_END;
            st_half4(g_NX + j * 4, ((const float4*)NX)[j]);
        } else {
            long j = i - R4_END;
            st_half4(g_NY + j * 4, ((const float4*)NY)[j]);
        }
    }
}

// Stage sizes in halves. K-chunk 32. A rows x 40 (32 + 8 pad), B 32 x 136.
#define A1S (128 * 40)
#define A2S (64 * 40)
#define BKS (32 * 136)
#define SMEM_G1_BYTES (3 * (A1S + BKS) * 2)   // 56.8 KB -> dynamic

// ---------------------------------------------------------------------------
// GEMM1: [4096x576] @ g_W1[576x2048] + bias, relu -> g_H (fp16).
// 128x128 tile, 256 thr, warps 2m x 4n (64x32). K32, 3-stage cp.async.
// grid (16, 32) = 512 blocks.
// ---------------------------------------------------------------------------
__global__ __launch_bounds__(256, 2) void k_gemm1(
    const float* __restrict__ bx1, const float* __restrict__ by1) {
    const int bm = blockIdx.y * 128, bnG = blockIdx.x * 128;
    const float* bias = (bnG < 1024) ? bx1 : by1;
    const int bn = bnG & 1023;

    extern __shared__ __half smem[];
    __half* Asm = smem;
    __half* Bsm = smem + 3 * A1S;

    const int tid = threadIdx.x;
    const int warp = tid >> 5;
    const int mOff = (warp >> 2) * 64, nOff = (warp & 3) * 32;
    const int aRow = tid >> 1, aC = (tid & 1) * 16;   // halves
    const int bRow = tid >> 3, bC = (tid & 7) * 16;   // halves

    const int grow = bm + aRow;
    const __half* aState = g_state + (size_t)grow * 512;
    const __half* aEmb   = g_emb + g_opt[grow] * 64;

    float acc[16][4];
    #pragma unroll
    for (int i = 0; i < 16; i++)
        #pragma unroll
        for (int j = 0; j < 4; j++) acc[i][j] = 0.f;

    auto issue = [&](int stage, int k0) {
        const int gk = k0 + aC;
        const __half* sa = (gk < 512) ? (aState + gk) : (aEmb + (gk - 512));
        __half* ad = Asm + stage * A1S + aRow * 40 + aC;
        cpa16(ad, sa); cpa16(ad + 8, sa + 8);
        const __half* sb = g_W1 + (size_t)(k0 + bRow) * 2048 + bnG + bC;
        __half* bd = Bsm + stage * BKS + bRow * 136 + bC;
        cpa16(bd, sb); cpa16(bd + 8, sb + 8);
    };

    const int NC = 18;  // 576 / 32
    issue(0, 0);  CPA_COMMIT();
    issue(1, 32); CPA_COMMIT();
    for (int c = 0; c < NC; c++) {
        CPA_WAIT1();
        __syncthreads();
        if (c + 2 < NC) issue((c + 2) % 3, (c + 2) * 32);
        CPA_COMMIT();
        tile_compute_h<4, 4, 40, 32>(Asm + (c % 3) * A1S, Bsm + (c % 3) * BKS,
                                     mOff, nOff, acc);
    }

    const int lane = tid & 31, g = lane >> 2, t = lane & 3;
    #pragma unroll
    for (int mf = 0; mf < 4; mf++)
        #pragma unroll
        for (int nf = 0; nf < 4; nf++) {
            const float* ca = acc[mf * 4 + nf];
            const int ncl = nOff + nf * 8 + 2 * t;
            const float bv0 = bias[bn + ncl], bv1 = bias[bn + ncl + 1];
            const int r0 = bm + mOff + mf * 16 + g;
            *(__half2*)&g_H[(size_t)r0 * 2048 + bnG + ncl] =
                __floats2half2_rn(fmaxf(ca[0] + bv0, 0.f), fmaxf(ca[1] + bv1, 0.f));
            *(__half2*)&g_H[(size_t)(r0 + 8) * 2048 + bnG + ncl] =
                __floats2half2_rn(fmaxf(ca[2] + bv0, 0.f), fmaxf(ca[3] + bv1, 0.f));
        }
}

// ---------------------------------------------------------------------------
// GEMM2: cls = H @ g_W2 + bias (K=1024). 64x128 tile, 256 thr,
// warps 2m x 4n of 32x32. K32, 3-stage. grid (4, 64) = 256 blocks.
// ---------------------------------------------------------------------------
__global__ __launch_bounds__(256, 2) void k_gemm2(
    const float* __restrict__ bx2, const float* __restrict__ by2) {
    const int bm = blockIdx.y * 64, bnG = blockIdx.x * 128;
    const float* bias = (bnG < 256) ? bx2 : by2;
    const int bn = bnG & 255;
    const int aOff = (bnG < 256) ? 0 : 1024;

    __shared__ __half Asm[3 * A2S];
    __shared__ __half Bsm[3 * BKS];

    const int tid = threadIdx.x;
    const int warp = tid >> 5;
    const int mOff = (warp >> 2) * 32, nOff = (warp & 3) * 32;
    const int aRow = tid >> 2, aC = (tid & 3) * 8;
    const int bRow = tid >> 3, bC = (tid & 7) * 16;

    const __half* aPtr = g_H + (size_t)(bm + aRow) * 2048 + aOff;

    float acc[8][4];
    #pragma unroll
    for (int i = 0; i < 8; i++)
        #pragma unroll
        for (int j = 0; j < 4; j++) acc[i][j] = 0.f;

    auto issue = [&](int stage, int k0) {
        __half* ad = Asm + stage * A2S + aRow * 40 + aC;
        cpa16(ad, aPtr + k0 + aC);
        const __half* sb = g_W2 + (size_t)(k0 + bRow) * 512 + bnG + bC;
        __half* bd = Bsm + stage * BKS + bRow * 136 + bC;
        cpa16(bd, sb); cpa16(bd + 8, sb + 8);
    };

    const int NC = 32;  // 1024 / 32
    issue(0, 0);  CPA_COMMIT();
    issue(1, 32); CPA_COMMIT();
    for (int c = 0; c < NC; c++) {
        CPA_WAIT1();
        __syncthreads();
        if (c + 2 < NC) issue((c + 2) % 3, (c + 2) * 32);
        CPA_COMMIT();
        tile_compute_h<2, 4, 40, 32>(Asm + (c % 3) * A2S, Bsm + (c % 3) * BKS,
                                     mOff, nOff, acc);
    }

    const int lane = tid & 31, g = lane >> 2, t = lane & 3;
    #pragma unroll
    for (int mf = 0; mf < 2; mf++)
        #pragma unroll
        for (int nf = 0; nf < 4; nf++) {
            const float* ca = acc[mf * 4 + nf];
            const int ncl = nOff + nf * 8 + 2 * t;
            const float bv0 = bias[bn + ncl], bv1 = bias[bn + ncl + 1];
            const int r0 = bm + mOff + mf * 16 + g;
            *(__half2*)&g_cls[(size_t)r0 * 512 + bnG + ncl] =
                __floats2half2_rn(ca[0] + bv0, ca[1] + bv1);
            *(__half2*)&g_cls[(size_t)(r0 + 8) * 512 + bnG + ncl] =
                __floats2half2_rn(ca[2] + bv0, ca[3] + bv1);
        }
}

// ---------------------------------------------------------------------------
// GEMM X+Y fused (256 blocks, 256 threads). Both paths: 64-row tiles,
// K=256 in 8 K32 chunks, 3-stage cp.async.
//   blocks [0,128):  out_X = cls_X @ g_NX
//   blocks [128,256): grouped out_Y per class (A rows gathered via perm;
//                     zero-filled for padding rows; B from fp16 g_NY)
// ---------------------------------------------------------------------------
__global__ __launch_bounds__(256, 2) void k_gemmxy(
    float* __restrict__ out) {
    __shared__ __half Asm[3 * A2S];
    __shared__ __half Bsm[3 * BKS];
    __shared__ int rowIdx[64];

    const int tid = threadIdx.x;
    const int warp = tid >> 5;
    const int lane = tid & 31, g = lane >> 2, t = lane & 3;
    const int mOff = (warp >> 2) * 32, nOff = (warp & 3) * 32;
    const int aRow = tid >> 2, aC = (tid & 3) * 8;
    const int bRow = tid >> 3, bC = (tid & 7) * 16;

    if (blockIdx.x < 128) {
        // ----- X path: 64x128 tile -----
        const int bm = (blockIdx.x >> 1) * 64, bn = (blockIdx.x & 1) * 128;
        const __half* aPtr = g_cls + (size_t)(bm + aRow) * 512;

        float acc[8][4];
        #pragma unroll
        for (int i = 0; i < 8; i++)
            #pragma unroll
            for (int j = 0; j < 4; j++) acc[i][j] = 0.f;

        auto issue = [&](int stage, int k0) {
            __half* ad = Asm + stage * A2S + aRow * 40 + aC;
            cpa16(ad, aPtr + k0 + aC);
            const __half* sb = g_NX + (size_t)(k0 + bRow) * 256 + bn + bC;
            __half* bd = Bsm + stage * BKS + bRow * 136 + bC;
            cpa16(bd, sb); cpa16(bd + 8, sb + 8);
        };

        const int NC = 8;
        issue(0, 0);  CPA_COMMIT();
        issue(1, 32); CPA_COMMIT();
        for (int c = 0; c < NC; c++) {
            CPA_WAIT1();
            __syncthreads();
            if (c + 2 < NC) issue((c + 2) % 3, (c + 2) * 32);
            CPA_COMMIT();
            tile_compute_h<2, 4, 40, 32>(Asm + (c % 3) * A2S, Bsm + (c % 3) * BKS,
                                         mOff, nOff, acc);
        }
        #pragma unroll
        for (int mf = 0; mf < 2; mf++)
            #pragma unroll
            for (int nf = 0; nf < 4; nf++) {
                const float* ca = acc[mf * 4 + nf];
                const int ncl = nOff + nf * 8 + 2 * t;
                const int r0 = bm + mOff + mf * 16 + g;
                *(float2*)&out[(size_t)r0 * 256 + bn + ncl] = make_float2(ca[0], ca[1]);
                *(float2*)&out[(size_t)(r0 + 8) * 256 + bn + ncl] = make_float2(ca[2], ca[3]);
            }
    } else {
        // ----- Y path: per-class 64-row chunks, same pipeline -----
        float* outY = out + (size_t)4096 * 256;
        const int yb = blockIdx.x - 128;
        const int cls = yb >> 1;
        const int bn  = (yb & 1) * 128;
        const int start = g_offsets[cls], end = g_offsets[cls + 1];
        const __half* Bmat = g_NY + (size_t)cls * 65536;

        for (int chunk = start; chunk < end; chunk += 64) {
            if (tid < 64) rowIdx[tid] = (chunk + tid < end) ? g_perm[chunk + tid] : -1;
            __syncthreads();

            float acc[8][4];
            #pragma unroll
            for (int i = 0; i < 8; i++)
                #pragma unroll
                for (int j = 0; j < 4; j++) acc[i][j] = 0.f;

            const int myRow = rowIdx[aRow];
            const __half* aSrc = g_cls + (myRow >= 0 ? (size_t)myRow * 512 + 256 : 0);
            auto issue = [&](int stage, int k0) {
                __half* ad = Asm + stage * A2S + aRow * 40 + aC;
                cpa16z(ad, aSrc + k0 + aC, myRow >= 0);
                const __half* sb = Bmat + (size_t)(k0 + bRow) * 256 + bn + bC;
                __half* bd = Bsm + stage * BKS + bRow * 136 + bC;
                cpa16(bd, sb); cpa16(bd + 8, sb + 8);
            };

            const int NC = 8;
            issue(0, 0);  CPA_COMMIT();
            issue(1, 32); CPA_COMMIT();
            for (int c = 0; c < NC; c++) {
                CPA_WAIT1();
                __syncthreads();
                if (c + 2 < NC) issue((c + 2) % 3, (c + 2) * 32);
                CPA_COMMIT();
                tile_compute_h<2, 4, 40, 32>(Asm + (c % 3) * A2S, Bsm + (c % 3) * BKS,
                                             mOff, nOff, acc);
            }

            #pragma unroll
            for (int mf = 0; mf < 2; mf++)
                #pragma unroll
                for (int nf = 0; nf < 4; nf++) {
                    const float* ca = acc[mf * 4 + nf];
                    const int ncol = bn + nOff + nf * 8 + 2 * t;
                    const int lr = mOff + mf * 16 + g;
                    const int r0 = rowIdx[lr], r1 = rowIdx[lr + 8];
                    if (r0 >= 0)
                        *(float2*)&outY[(size_t)r0 * 256 + ncol] = make_float2(ca[0], ca[1]);
                    if (r1 >= 0)
                        *(float2*)&outY[(size_t)r1 * 256 + ncol] = make_float2(ca[2], ca[3]);
                }
            __syncthreads();  // protect rowIdx / smem before next chunk
        }
    }
}

// ---------------------------------------------------------------------------
// Launch. Inputs: 0 state, 1 option, 2 embed, 3 Wx1, 4 bx1, 5 Wx2, 6 bx2,
// 7 Wy1, 8 by1, 9 Wy2, 10 by2, 11 NX, 12 NY. Output: [out_X | out_Y] fp32.
// ---------------------------------------------------------------------------
extern "C" void kernel_launch(void* const* d_in, const int* in_sizes, int n_in,
                              void* d_out, int out_size) {
    const float* state  = (const float*)d_in[0];
    const int*   optraw = (const int*)d_in[1];
    const float* embed  = (const float*)d_in[2];
    const float* Wx1 = (const float*)d_in[3];
    const float* bx1 = (const float*)d_in[4];
    const float* Wx2 = (const float*)d_in[5];
    const float* bx2 = (const float*)d_in[6];
    const float* Wy1 = (const float*)d_in[7];
    const float* by1 = (const float*)d_in[8];
    const float* Wy2 = (const float*)d_in[9];
    const float* by2 = (const float*)d_in[10];
    const float* NX  = (const float*)d_in[11];
    const float* NY  = (const float*)d_in[12];
    float* out = (float*)d_out;

    // >48KB dynamic smem opt-in for gemm1 (idempotent host call; no alloc).
    cudaFuncSetAttribute(k_gemm1, cudaFuncAttributeMaxDynamicSharedMemorySize,
                         SMEM_G1_BYTES);

    k_cvtprep<<<1037, 256>>>(state, embed, Wx1, Wy1, Wx2, Wy2, NX, NY, optraw);
    k_gemm1<<<dim3(16, 32), 256, SMEM_G1_BYTES>>>(bx1, by1);
    k_gemm2<<<dim3(4, 64), 256>>>(bx2, by2);
    k_gemmxy<<<256, 256>>>(out);
}